// round 6
// baseline (speedup 1.0000x reference)
#include <cuda_runtime.h>
#include <cstdint>
#include <cstddef>

#define BATCH 16
#define CDIM  512
#define EDIM  256
#define NDIM  2048

#define MT 128
#define NT 256
#define NSTG 3
#define A_BYTES 16384                 // 128 rows x 128B
#define STG_BYTES 49152               // A 16KB + B 32KB
#define SMEM_TOTAL (NSTG * STG_BYTES) // 144KB

// ---- scratch (alloc-free rule: __device__ globals) ----
__device__ float g_inA_t[(size_t)BATCH * NDIM * CDIM];
__device__ float g_inB_t[(size_t)BATCH * NDIM * CDIM];
__device__ float g_WA_r [(size_t)EDIM * CDIM];
__device__ float g_WB_r [(size_t)EDIM * CDIM];
__device__ float g_WBh_r[(size_t)EDIM * CDIM];
__device__ float g_Wout_r[(size_t)CDIM * EDIM];
__device__ float g_aproj_t[(size_t)BATCH * NDIM * EDIM];   // [pos][e]
__device__ float g_bp_t   [(size_t)BATCH * NDIM * EDIM];   // [pos][e]
__device__ float g_bh     [(size_t)BATCH * EDIM * NDIM];   // [e][pos]
__device__ float g_out1_t [(size_t)BATCH * NDIM * EDIM];   // [a][e]
__device__ float g_mean [CDIM];
__device__ float g_rstd [CDIM];

// ---- tf32 / mma helpers ----
__device__ __forceinline__ uint32_t f2tf32(float x) {
    uint32_t r; asm("cvt.rna.tf32.f32 %0, %1;" : "=r"(r) : "f"(x)); return r;
}
__device__ __forceinline__ float rndf(float x) { return __uint_as_float(f2tf32(x)); }

__device__ __forceinline__ void mma_tf32(float4& d,
                                         uint32_t a0, uint32_t a1, uint32_t a2, uint32_t a3,
                                         uint32_t b0, uint32_t b1) {
    asm volatile("mma.sync.aligned.m16n8k8.row.col.f32.tf32.tf32.f32 "
                 "{%0,%1,%2,%3}, {%4,%5,%6,%7}, {%8,%9}, {%0,%1,%2,%3};"
                 : "+f"(d.x), "+f"(d.y), "+f"(d.z), "+f"(d.w)
                 : "r"(a0), "r"(a1), "r"(a2), "r"(a3), "r"(b0), "r"(b1));
}
__device__ __forceinline__ void ldsm_x4(uint32_t& r0, uint32_t& r1,
                                        uint32_t& r2, uint32_t& r3, uint32_t addr) {
    asm volatile("ldmatrix.sync.aligned.m8n8.x4.shared.b16 {%0,%1,%2,%3}, [%4];"
                 : "=r"(r0), "=r"(r1), "=r"(r2), "=r"(r3) : "r"(addr));
}
__device__ __forceinline__ void cp16(uint32_t dst, const void* src) {
    asm volatile("cp.async.cg.shared.global [%0], [%1], 16;" :: "r"(dst), "l"(src));
}
#define CP_COMMIT() asm volatile("cp.async.commit_group;")
#define CP_WAIT1()  asm volatile("cp.async.wait_group 1;")

// swizzle for 128B rows: XOR byte-col bits[4:6] with row bits[0:2]
__device__ __forceinline__ uint32_t swz(uint32_t row, uint32_t colbyte) {
    return (row << 7) | (colbyte ^ ((row & 7) << 4));
}

// ============================================================================
// Pipelined TF32 mma.sync GEMM, operands contraction-contiguous:
//   C[m,n] = alpha * sum_k A[m][k]*B[n][k]
// Block tile 128(m) x 256(n), BK=32, 3-stage cp.async, 512 threads,
// 16 warps (2 m x 8 n), warp tile 64x32, m16n8k8, ldmatrix-fed fragments.
// CVT_A: rna-round the A tile in smem before compute (for raw-fp32 A = att).
// ============================================================================
template<bool ROUND, bool CVT_A>
__global__ __launch_bounds__(512, 1)
void gemm_mm(const float* __restrict__ Ag, const float* __restrict__ Bg,
             float* __restrict__ Cg, int K, int lda, int ldb, int ldc,
             size_t sA, size_t sB, size_t sC, float alpha)
{
    extern __shared__ __align__(16) char dynsmem[];
    const uint32_t smBase = (uint32_t)__cvta_generic_to_shared(dynsmem);

    const float* A = Ag + (size_t)blockIdx.z * sA;
    const float* B = Bg + (size_t)blockIdx.z * sB;
    float*       C = Cg + (size_t)blockIdx.z * sC;

    const int m0 = blockIdx.y * MT;
    const int n0 = blockIdx.x * NT;
    const int tid  = threadIdx.x;
    const int lane = tid & 31;
    const int wid  = tid >> 5;
    const int warp_m = wid & 1;    // 2 -> 64 m-rows each
    const int warp_n = wid >> 1;   // 8 -> 32 n-cols each

    // ldmatrix lane selectors (validated R3/R4 mapping)
    const int a_row = (lane & 7) + ((lane >> 3) & 1) * 8;
    const int a_ts  = ((lane >> 4) & 1) << 4;
    const int b_row = (lane & 7) + ((lane >> 4) & 1) * 8;
    const int b_ts  = ((lane >> 3) & 1) << 4;

    uint32_t aRow[4], bRow[2];
    #pragma unroll
    for (int i = 0; i < 4; i++)
        aRow[i] = (uint32_t)((warp_m * 64 + i * 16 + a_row) << 7);
    #pragma unroll
    for (int j = 0; j < 2; j++)
        bRow[j] = (uint32_t)A_BYTES + (uint32_t)((warp_n * 32 + j * 16 + b_row) << 7);
    const uint32_t aSwz = (uint32_t)((a_row & 7) << 4);
    const uint32_t bSwz = (uint32_t)((b_row & 7) << 4);

    // staging: 512 threads; A 2 chunks/thread (rows r*64), B 4 chunks/thread
    const int ld_row = tid >> 3;                 // 0..63
    const int ld_kq  = (tid & 7) << 2;           // k elem 0,4,..,28
    const uint32_t ld_off = swz((uint32_t)ld_row, (uint32_t)(ld_kq << 2));

    const int T = K >> 5;

    float4 acc[4][4];
    #pragma unroll
    for (int i = 0; i < 4; i++)
        #pragma unroll
        for (int j = 0; j < 4; j++)
            acc[i][j] = make_float4(0.f, 0.f, 0.f, 0.f);

    // ---- prologue: fill stages 0,1 ----
    #pragma unroll
    for (int s = 0; s < 2; s++) {
        const uint32_t st = smBase + s * STG_BYTES;
        const int k0 = s * 32;
        #pragma unroll
        for (int r = 0; r < 2; r++)
            cp16(st + ld_off + (uint32_t)(r * 64 * 128),
                 A + (size_t)(m0 + ld_row + r * 64) * lda + (k0 + ld_kq));
        #pragma unroll
        for (int r = 0; r < 4; r++)
            cp16(st + A_BYTES + ld_off + (uint32_t)(r * 64 * 128),
                 B + (size_t)(n0 + ld_row + r * 64) * ldb + (k0 + ld_kq));
        CP_COMMIT();
    }

    int scur = 0;          // stage of tile t
    int spre = 2;          // stage of tile t+2
    for (int t = 0; t < T; t++) {
        CP_WAIT1();               // tile t resident (t+1 may be in flight)
        __syncthreads();

        if (CVT_A) {
            // rna-round A tile in place (bitwise == pre-rounded operand)
            float4* pa = (float4*)(dynsmem + scur * STG_BYTES);
            float4 v0 = pa[tid], v1 = pa[tid + 512];
            v0.x = rndf(v0.x); v0.y = rndf(v0.y); v0.z = rndf(v0.z); v0.w = rndf(v0.w);
            v1.x = rndf(v1.x); v1.y = rndf(v1.y); v1.z = rndf(v1.z); v1.w = rndf(v1.w);
            pa[tid] = v0; pa[tid + 512] = v1;
            __syncthreads();
        }

        // issue tile t+2 (after barrier: stage spre's previous readers are done)
        if (t + 2 < T) {
            const uint32_t st = smBase + spre * STG_BYTES;
            const int k0 = (t + 2) * 32;
            #pragma unroll
            for (int r = 0; r < 2; r++)
                cp16(st + ld_off + (uint32_t)(r * 64 * 128),
                     A + (size_t)(m0 + ld_row + r * 64) * lda + (k0 + ld_kq));
            #pragma unroll
            for (int r = 0; r < 4; r++)
                cp16(st + A_BYTES + ld_off + (uint32_t)(r * 64 * 128),
                     B + (size_t)(n0 + ld_row + r * 64) * ldb + (k0 + ld_kq));
        }
        CP_COMMIT();

        // ---- compute stage scur ----
        const uint32_t sb = smBase + scur * STG_BYTES;
        #pragma unroll
        for (int ks = 0; ks < 4; ks++) {
            const uint32_t aCol = ((uint32_t)(ks * 32) + a_ts) ^ aSwz;
            const uint32_t bCol = ((uint32_t)(ks * 32) + b_ts) ^ bSwz;
            uint32_t af[4][4], bf[2][4];
            #pragma unroll
            for (int i = 0; i < 4; i++)
                ldsm_x4(af[i][0], af[i][1], af[i][2], af[i][3], sb + aRow[i] + aCol);
            #pragma unroll
            for (int j = 0; j < 2; j++)
                ldsm_x4(bf[j][0], bf[j][1], bf[j][2], bf[j][3], sb + bRow[j] + bCol);
            #pragma unroll
            for (int i = 0; i < 4; i++) {
                #pragma unroll
                for (int jn = 0; jn < 4; jn++) {
                    int jx = jn >> 1, h = (jn & 1) << 1;
                    mma_tf32(acc[i][jn], af[i][0], af[i][1], af[i][2], af[i][3],
                             bf[jx][h], bf[jx][h + 1]);
                }
            }
        }
        scur = (scur == 2) ? 0 : scur + 1;
        spre = (spre == 2) ? 0 : spre + 1;
    }

    // ---- epilogue ----
    const int g = lane >> 2, tq = lane & 3;
    const int mw = m0 + warp_m * 64;
    const int nw = n0 + warp_n * 32;
    #pragma unroll
    for (int i = 0; i < 4; i++) {
        #pragma unroll
        for (int jn = 0; jn < 4; jn++) {
            int row = mw + i * 16 + g;
            int col = nw + jn * 8 + 2 * tq;
            float2 v0 = make_float2(acc[i][jn].x * alpha, acc[i][jn].y * alpha);
            float2 v1 = make_float2(acc[i][jn].z * alpha, acc[i][jn].w * alpha);
            if (ROUND) {
                v0.x = rndf(v0.x); v0.y = rndf(v0.y);
                v1.x = rndf(v1.x); v1.y = rndf(v1.y);
            }
            *(float2*)(C + (size_t)row * ldc + col)       = v0;
            *(float2*)(C + (size_t)(row + 8) * ldc + col) = v1;
        }
    }
}

// ============================================================================
// transpose + tf32-round: [C][N] -> [N][C] per batch.
// ============================================================================
__global__ __launch_bounds__(256)
void transpose_round(const float* __restrict__ in, float* __restrict__ outp)
{
    __shared__ float tile[32][33];
    const float* src = in   + (size_t)blockIdx.z * CDIM * NDIM;
    float*       dst = outp + (size_t)blockIdx.z * NDIM * CDIM;

    int x = blockIdx.x * 32 + threadIdx.x;
    #pragma unroll
    for (int i = 0; i < 4; i++) {
        int c = blockIdx.y * 32 + threadIdx.y + i * 8;
        tile[threadIdx.y + i * 8][threadIdx.x] = src[(size_t)c * NDIM + x];
    }
    __syncthreads();
    int xo = blockIdx.y * 32 + threadIdx.x;
    #pragma unroll
    for (int i = 0; i < 4; i++) {
        int n = blockIdx.x * 32 + threadIdx.y + i * 8;
        dst[(size_t)n * CDIM + xo] = rndf(tile[threadIdx.x][threadIdx.y + i * 8]);
    }
}

__global__ __launch_bounds__(256)
void round_copy(const float* __restrict__ in, float* __restrict__ outp)
{
    size_t i = ((size_t)blockIdx.x * 256 + threadIdx.x) * 4;
    float4 v = *(const float4*)(in + i);
    v.x = rndf(v.x); v.y = rndf(v.y); v.z = rndf(v.z); v.w = rndf(v.w);
    *(float4*)(outp + i) = v;
}

// ============================================================================
// In-place row softmax over rows of length 2048.
// ============================================================================
__global__ __launch_bounds__(256)
void softmax2048(float* __restrict__ att)
{
    float* p = att + (size_t)blockIdx.x * NDIM;
    const int t = threadIdx.x;

    float x[8];
    *(float4*)&x[0] = *(const float4*)(p + t * 4);
    *(float4*)&x[4] = *(const float4*)(p + 1024 + t * 4);

    float mx = x[0];
    #pragma unroll
    for (int i = 1; i < 8; i++) mx = fmaxf(mx, x[i]);
    #pragma unroll
    for (int o = 16; o > 0; o >>= 1) mx = fmaxf(mx, __shfl_xor_sync(0xffffffffu, mx, o));

    __shared__ float rmax[8], rsum[8];
    if ((t & 31) == 0) rmax[t >> 5] = mx;
    __syncthreads();
    mx = rmax[0];
    #pragma unroll
    for (int w = 1; w < 8; w++) mx = fmaxf(mx, rmax[w]);

    float s = 0.f;
    #pragma unroll
    for (int i = 0; i < 8; i++) { x[i] = __expf(x[i] - mx); s += x[i]; }
    #pragma unroll
    for (int o = 16; o > 0; o >>= 1) s += __shfl_xor_sync(0xffffffffu, s, o);
    if ((t & 31) == 0) rsum[t >> 5] = s;
    __syncthreads();
    s = 0.f;
    #pragma unroll
    for (int w = 0; w < 8; w++) s += rsum[w];

    float inv = 1.0f / s;
    #pragma unroll
    for (int i = 0; i < 8; i++) x[i] *= inv;
    *(float4*)(p + t * 4)        = *(float4*)&x[0];
    *(float4*)(p + 1024 + t * 4) = *(float4*)&x[4];
}

// ============================================================================
// BatchNorm
// ============================================================================
__global__ __launch_bounds__(256)
void bn_stats(const float* __restrict__ outp,
              float* __restrict__ mean, float* __restrict__ rstd)
{
    const int c = blockIdx.x;
    const int t = threadIdx.x;
    float s = 0.f, ss = 0.f;
    for (int b = 0; b < BATCH; b++) {
        const float* p = outp + (size_t)b * CDIM * NDIM + (size_t)c * NDIM;
        for (int a = t; a < NDIM; a += 256) {
            float x = p[a];
            s += x;
            ss = fmaf(x, x, ss);
        }
    }
    #pragma unroll
    for (int o = 16; o > 0; o >>= 1) {
        s  += __shfl_xor_sync(0xffffffffu, s,  o);
        ss += __shfl_xor_sync(0xffffffffu, ss, o);
    }
    __shared__ float rs[8], rss[8];
    if ((t & 31) == 0) { rs[t >> 5] = s; rss[t >> 5] = ss; }
    __syncthreads();
    if (t == 0) {
        float S = 0.f, SS = 0.f;
        #pragma unroll
        for (int w = 0; w < 8; w++) { S += rs[w]; SS += rss[w]; }
        const float invN = 1.0f / (float)(BATCH * NDIM);
        float m = S * invN;
        float var = SS * invN - m * m;
        mean[c] = m;
        rstd[c] = rsqrtf(var + 1e-5f);
    }
}

__global__ __launch_bounds__(256)
void bn_norm(float* __restrict__ outp,
             const float* __restrict__ mean, const float* __restrict__ rstd,
             const float* __restrict__ gamma, const float* __restrict__ beta)
{
    size_t i = ((size_t)blockIdx.x * 256 + threadIdx.x) * 4;
    int c = (int)((i / NDIM) % CDIM);
    float m = mean[c], r = rstd[c];
    float sc = r * gamma[c];
    float sh = beta[c] - m * sc;
    float4 v = *(float4*)(outp + i);
    v.x = fmaf(v.x, sc, sh);
    v.y = fmaf(v.y, sc, sh);
    v.z = fmaf(v.z, sc, sh);
    v.w = fmaf(v.w, sc, sh);
    *(float4*)(outp + i) = v;
}

// ============================================================================
extern "C" void kernel_launch(void* const* d_in, const int* in_sizes, int n_in,
                              void* d_out, int out_size)
{
    (void)in_sizes; (void)n_in; (void)out_size;
    const float* input_A = (const float*)d_in[0];
    const float* input_B = (const float*)d_in[1];
    const float* W_A     = (const float*)d_in[2];
    const float* W_B     = (const float*)d_in[3];
    const float* W_Bh    = (const float*)d_in[4];
    const float* W_out   = (const float*)d_in[5];
    const float* gamma   = (const float*)d_in[6];
    const float* beta    = (const float*)d_in[7];

    float* out = (float*)d_out;
    float* att = out + (size_t)BATCH * CDIM * NDIM;

    float *inA_t, *inB_t, *WA_r, *WB_r, *WBh_r, *Wout_r;
    float *aproj_t, *bp_t, *bh, *out1_t, *mean, *rstd;
    cudaGetSymbolAddress((void**)&inA_t,   g_inA_t);
    cudaGetSymbolAddress((void**)&inB_t,   g_inB_t);
    cudaGetSymbolAddress((void**)&WA_r,    g_WA_r);
    cudaGetSymbolAddress((void**)&WB_r,    g_WB_r);
    cudaGetSymbolAddress((void**)&WBh_r,   g_WBh_r);
    cudaGetSymbolAddress((void**)&Wout_r,  g_Wout_r);
    cudaGetSymbolAddress((void**)&aproj_t, g_aproj_t);
    cudaGetSymbolAddress((void**)&bp_t,    g_bp_t);
    cudaGetSymbolAddress((void**)&bh,      g_bh);
    cudaGetSymbolAddress((void**)&out1_t,  g_out1_t);
    cudaGetSymbolAddress((void**)&mean,    g_mean);
    cudaGetSymbolAddress((void**)&rstd,    g_rstd);

    cudaFuncSetAttribute(gemm_mm<true,  false>, cudaFuncAttributeMaxDynamicSharedMemorySize, SMEM_TOTAL);
    cudaFuncSetAttribute(gemm_mm<false, false>, cudaFuncAttributeMaxDynamicSharedMemorySize, SMEM_TOTAL);
    cudaFuncSetAttribute(gemm_mm<true,  true>,  cudaFuncAttributeMaxDynamicSharedMemorySize, SMEM_TOTAL);

    const dim3 blk(512);
    const size_t sNC = (size_t)NDIM * CDIM;
    const size_t sNE = (size_t)NDIM * EDIM;
    const size_t sEN = (size_t)EDIM * NDIM;
    const size_t sCN = (size_t)CDIM * NDIM;
    const size_t sNN = (size_t)NDIM * NDIM;

    // 0) preprocess: transpose+round inputs, round weights
    dim3 gt(NDIM / 32, CDIM / 32, BATCH);
    transpose_round<<<gt, dim3(32, 8)>>>(input_A, inA_t);
    transpose_round<<<gt, dim3(32, 8)>>>(input_B, inB_t);
    round_copy<<<(EDIM * CDIM) / 1024, 256>>>(W_A,   WA_r);
    round_copy<<<(EDIM * CDIM) / 1024, 256>>>(W_B,   WB_r);
    round_copy<<<(EDIM * CDIM) / 1024, 256>>>(W_Bh,  WBh_r);
    round_copy<<<(CDIM * EDIM) / 1024, 256>>>(W_out, Wout_r);

    // 1) projections
    // aproj_t[pos][e]: m=pos(2048), n=e(256), k=c(512)
    dim3 gpa(EDIM / NT, NDIM / MT, BATCH);
    gemm_mm<true, false><<<gpa, blk, SMEM_TOTAL>>>(inA_t, WA_r, aproj_t, CDIM, CDIM, CDIM, EDIM, sNC, 0, sNE, 1.f);
    gemm_mm<true, false><<<gpa, blk, SMEM_TOTAL>>>(inB_t, WB_r, bp_t,    CDIM, CDIM, CDIM, EDIM, sNC, 0, sNE, 1.f);
    // bh[e][pos]: m=e(256), n=pos(2048), k=c(512)
    dim3 gpb(NDIM / NT, EDIM / MT, BATCH);
    gemm_mm<true, false><<<gpb, blk, SMEM_TOTAL>>>(WBh_r, inB_t, bh,     CDIM, CDIM, CDIM, NDIM, 0, sNC, sEN, 1.f);

    // 2) h[a][b] = (aproj_t · bp_t^T)/16 : m=a(2048), n=b(2048), k=e(256)
    dim3 gh(NDIM / NT, NDIM / MT, BATCH);
    gemm_mm<false, false><<<gh, blk, SMEM_TOTAL>>>(aproj_t, bp_t, att, EDIM, EDIM, EDIM, NDIM, sNE, sNE, sNN, 0.0625f);

    // 3) in-place softmax
    softmax2048<<<BATCH * NDIM, 256>>>(att);

    // 4) out1_t[a][e]: m=a(2048), n=e(256), k=pos(2048); A=att raw fp32 -> CVT_A
    dim3 g4(EDIM / NT, NDIM / MT, BATCH);
    gemm_mm<true, true><<<g4, blk, SMEM_TOTAL>>>(att, bh, out1_t, NDIM, NDIM, NDIM, EDIM, sNN, sEN, sNE, 1.f);

    // 5) out[c][a]: m=c(512), n=a(2048), k=e(256)
    dim3 g5(NDIM / NT, CDIM / MT, BATCH);
    gemm_mm<false, false><<<g5, blk, SMEM_TOTAL>>>(Wout_r, out1_t, out, EDIM, EDIM, EDIM, NDIM, 0, sNE, sCN, 1.f);

    // 6) BatchNorm
    bn_stats<<<CDIM, 256>>>(out, mean, rstd);
    bn_norm<<<(BATCH * CDIM * NDIM) / 1024, 256>>>(out, mean, rstd, gamma, beta);
}

// round 7
// speedup vs baseline: 1.0346x; 1.0346x over previous
#include <cuda_runtime.h>
#include <cstdint>
#include <cstddef>

#define BATCH 16
#define CDIM  512
#define EDIM  256
#define NDIM  2048
#define STAGES 3
#define STAGE_BYTES 32768            // 16KB A + 16KB B
#define SMEM_BYTES (STAGES * STAGE_BYTES)

// ---- scratch (alloc-free rule: __device__ globals) ----
__device__ float g_inA_t[(size_t)BATCH * NDIM * CDIM];
__device__ float g_inB_t[(size_t)BATCH * NDIM * CDIM];
__device__ float g_WA_r [(size_t)EDIM * CDIM];
__device__ float g_WB_r [(size_t)EDIM * CDIM];
__device__ float g_WBh_r[(size_t)EDIM * CDIM];
__device__ float g_Wout_r[(size_t)CDIM * EDIM];
__device__ float g_aproj_t[(size_t)BATCH * NDIM * EDIM];   // [pos][e]
__device__ float g_bp_t   [(size_t)BATCH * NDIM * EDIM];   // [pos][e]
__device__ float g_bh     [(size_t)BATCH * EDIM * NDIM];   // [e][pos]
__device__ float g_out1_t [(size_t)BATCH * NDIM * EDIM];   // [a][e]
__device__ float g_mean [CDIM];
__device__ float g_rstd [CDIM];

// ---- tf32 / mma helpers ----
__device__ __forceinline__ uint32_t f2tf32(float x) {
    uint32_t r; asm("cvt.rna.tf32.f32 %0, %1;" : "=r"(r) : "f"(x)); return r;
}
__device__ __forceinline__ float rndf(float x) { return __uint_as_float(f2tf32(x)); }

__device__ __forceinline__ void mma_tf32(float4& d,
                                         uint32_t a0, uint32_t a1, uint32_t a2, uint32_t a3,
                                         uint32_t b0, uint32_t b1) {
    asm volatile("mma.sync.aligned.m16n8k8.row.col.f32.tf32.tf32.f32 "
                 "{%0,%1,%2,%3}, {%4,%5,%6,%7}, {%8,%9}, {%0,%1,%2,%3};"
                 : "+f"(d.x), "+f"(d.y), "+f"(d.z), "+f"(d.w)
                 : "r"(a0), "r"(a1), "r"(a2), "r"(a3), "r"(b0), "r"(b1));
}
__device__ __forceinline__ void ldsm_x4(uint32_t& r0, uint32_t& r1,
                                        uint32_t& r2, uint32_t& r3, uint32_t addr) {
    asm volatile("ldmatrix.sync.aligned.m8n8.x4.shared.b16 {%0,%1,%2,%3}, [%4];"
                 : "=r"(r0), "=r"(r1), "=r"(r2), "=r"(r3) : "r"(addr));
}
__device__ __forceinline__ void cp16(uint32_t dst, const void* src) {
    asm volatile("cp.async.cg.shared.global [%0], [%1], 16;" :: "r"(dst), "l"(src));
}
#define CP_COMMIT() asm volatile("cp.async.commit_group;")
#define CP_WAIT1()  asm volatile("cp.async.wait_group 1;")

// swizzle for 128B rows: XOR byte-col bits[4:6] with row bits[0:2]
__device__ __forceinline__ uint32_t swz(uint32_t row, uint32_t colbyte) {
    return (row << 7) | (colbyte ^ ((row & 7) << 4));
}

// ============================================================================
// Pipelined TF32 GEMM (R4-proven config). Operands contraction-contiguous:
//   A[m][k] (lda), B[n][k] (ldb)  ->  C[m][n] = alpha * sum_k A*B
// 128x128 block tile, BK=32, 3-stage cp.async, 256 threads, 2 CTAs/SM,
// 8 warps (2x4), warp tile 64x32, m16n8k8, ldmatrix-fed fragments.
// CVT_A: rna-round A tile in smem before compute (raw-fp32 A = att).
// ============================================================================
template<bool ROUND, bool CVT_A>
__global__ __launch_bounds__(256, 2)
void gemm_pipe(const float* __restrict__ Ag, const float* __restrict__ Bg,
               float* __restrict__ Cg, int K, int lda, int ldb, int ldc,
               size_t sA, size_t sB, size_t sC, float alpha)
{
    extern __shared__ __align__(16) char dynsmem[];
    const uint32_t smBase = (uint32_t)__cvta_generic_to_shared(dynsmem);

    const float* A = Ag + (size_t)blockIdx.z * sA;
    const float* B = Bg + (size_t)blockIdx.z * sB;
    float*       C = Cg + (size_t)blockIdx.z * sC;

    const int m0 = blockIdx.y * 128;
    const int n0 = blockIdx.x * 128;
    const int tid  = threadIdx.x;
    const int lane = tid & 31;
    const int wid  = tid >> 5;
    const int warp_m = wid >> 2;   // 0..1  -> 64 m-rows
    const int warp_n = wid & 3;    // 0..3  -> 32 n-cols

    const int a_row = (lane & 7) + ((lane >> 3) & 1) * 8;
    const int a_ts  = ((lane >> 4) & 1) << 4;
    const int b_row = (lane & 7) + ((lane >> 4) & 1) * 8;
    const int b_ts  = ((lane >> 3) & 1) << 4;

    uint32_t aRow[4], bRow[2];
    #pragma unroll
    for (int i = 0; i < 4; i++) aRow[i] = (uint32_t)((warp_m * 64 + i * 16 + a_row) << 7);
    #pragma unroll
    for (int j = 0; j < 2; j++) bRow[j] = (uint32_t)((warp_n * 32 + j * 16 + b_row) << 7) + 16384u;
    const uint32_t aSwz = (uint32_t)((a_row & 7) << 4);
    const uint32_t bSwz = (uint32_t)((b_row & 7) << 4);

    const int ld_row = tid >> 3;                 // 0..31 (+32 per r)
    const int ld_kq  = (tid & 7) << 2;           // k offset 0,4,..,28
    const uint32_t ld_dst = swz((uint32_t)ld_row, (uint32_t)(ld_kq << 2));

    const int T = K >> 5;

    float4 acc[4][4];
    #pragma unroll
    for (int i = 0; i < 4; i++)
        #pragma unroll
        for (int j = 0; j < 4; j++)
            acc[i][j] = make_float4(0.f, 0.f, 0.f, 0.f);

    // ---- prologue: fill stages 0,1 ----
    #pragma unroll
    for (int s = 0; s < 2; s++) {
        const uint32_t sa = smBase + s * STAGE_BYTES;
        const int k0 = s * 32;
        #pragma unroll
        for (int r = 0; r < 4; r++) {
            int row = ld_row + r * 32;
            cp16(sa + ld_dst + (uint32_t)(r * 32 * 128),
                 A + (size_t)(m0 + row) * lda + (k0 + ld_kq));
            cp16(sa + 16384u + ld_dst + (uint32_t)(r * 32 * 128),
                 B + (size_t)(n0 + row) * ldb + (k0 + ld_kq));
        }
        CP_COMMIT();
    }

    int stage = 0;
    for (int t = 0; t < T; t++) {
        CP_WAIT1();
        __syncthreads();

        if (CVT_A) {
            // rna-round the A tile in place (bitwise == pre-rounded operand)
            float4* pa = (float4*)(dynsmem + stage * STAGE_BYTES);
            float4 v0 = pa[tid];
            float4 v1 = pa[tid + 256];
            float4 v2 = pa[tid + 512];
            float4 v3 = pa[tid + 768];
            v0.x = rndf(v0.x); v0.y = rndf(v0.y); v0.z = rndf(v0.z); v0.w = rndf(v0.w);
            v1.x = rndf(v1.x); v1.y = rndf(v1.y); v1.z = rndf(v1.z); v1.w = rndf(v1.w);
            v2.x = rndf(v2.x); v2.y = rndf(v2.y); v2.z = rndf(v2.z); v2.w = rndf(v2.w);
            v3.x = rndf(v3.x); v3.y = rndf(v3.y); v3.z = rndf(v3.z); v3.w = rndf(v3.w);
            pa[tid] = v0; pa[tid + 256] = v1; pa[tid + 512] = v2; pa[tid + 768] = v3;
            __syncthreads();
        }

        // issue t+2 (stage (t+2)%3 == (t-1)%3, whose readers finished last iter)
        if (t + 2 < T) {
            int s2 = stage + 2; if (s2 >= STAGES) s2 -= STAGES;
            const uint32_t sa = smBase + s2 * STAGE_BYTES;
            const int k0 = (t + 2) * 32;
            #pragma unroll
            for (int r = 0; r < 4; r++) {
                int row = ld_row + r * 32;
                cp16(sa + ld_dst + (uint32_t)(r * 32 * 128),
                     A + (size_t)(m0 + row) * lda + (k0 + ld_kq));
                cp16(sa + 16384u + ld_dst + (uint32_t)(r * 32 * 128),
                     B + (size_t)(n0 + row) * ldb + (k0 + ld_kq));
            }
        }
        CP_COMMIT();

        // ---- compute current stage ----
        const uint32_t sb = smBase + stage * STAGE_BYTES;
        #pragma unroll
        for (int ks = 0; ks < 4; ks++) {
            const uint32_t aCol = ((uint32_t)(ks * 32) + a_ts) ^ aSwz;
            const uint32_t bCol = ((uint32_t)(ks * 32) + b_ts) ^ bSwz;
            uint32_t af[4][4], bf[2][4];
            #pragma unroll
            for (int i = 0; i < 4; i++)
                ldsm_x4(af[i][0], af[i][1], af[i][2], af[i][3], sb + aRow[i] + aCol);
            #pragma unroll
            for (int j = 0; j < 2; j++)
                ldsm_x4(bf[j][0], bf[j][1], bf[j][2], bf[j][3], sb + bRow[j] + bCol);
            #pragma unroll
            for (int i = 0; i < 4; i++) {
                #pragma unroll
                for (int jn = 0; jn < 4; jn++) {
                    int jx = jn >> 1, h = (jn & 1) << 1;
                    mma_tf32(acc[i][jn], af[i][0], af[i][1], af[i][2], af[i][3],
                             bf[jx][h], bf[jx][h + 1]);
                }
            }
        }
        stage++; if (stage >= STAGES) stage -= STAGES;
    }

    // ---- epilogue ----
    const int g = lane >> 2, tq = lane & 3;
    const int mw = m0 + warp_m * 64;
    const int nw = n0 + warp_n * 32;
    #pragma unroll
    for (int i = 0; i < 4; i++) {
        #pragma unroll
        for (int jn = 0; jn < 4; jn++) {
            int row = mw + i * 16 + g;
            int col = nw + jn * 8 + 2 * tq;
            float2 v0 = make_float2(acc[i][jn].x * alpha, acc[i][jn].y * alpha);
            float2 v1 = make_float2(acc[i][jn].z * alpha, acc[i][jn].w * alpha);
            if (ROUND) {
                v0.x = rndf(v0.x); v0.y = rndf(v0.y);
                v1.x = rndf(v1.x); v1.y = rndf(v1.y);
            }
            *(float2*)(C + (size_t)row * ldc + col)       = v0;
            *(float2*)(C + (size_t)(row + 8) * ldc + col) = v1;
        }
    }
}

// ============================================================================
// transpose + tf32-round: [C][N] -> [N][C] per batch.
// ============================================================================
__global__ __launch_bounds__(256)
void transpose_round(const float* __restrict__ in, float* __restrict__ outp)
{
    __shared__ float tile[32][33];
    const float* src = in   + (size_t)blockIdx.z * CDIM * NDIM;
    float*       dst = outp + (size_t)blockIdx.z * NDIM * CDIM;

    int x = blockIdx.x * 32 + threadIdx.x;
    #pragma unroll
    for (int i = 0; i < 4; i++) {
        int c = blockIdx.y * 32 + threadIdx.y + i * 8;
        tile[threadIdx.y + i * 8][threadIdx.x] = src[(size_t)c * NDIM + x];
    }
    __syncthreads();
    int xo = blockIdx.y * 32 + threadIdx.x;
    #pragma unroll
    for (int i = 0; i < 4; i++) {
        int n = blockIdx.x * 32 + threadIdx.y + i * 8;
        dst[(size_t)n * CDIM + xo] = rndf(tile[threadIdx.x][threadIdx.y + i * 8]);
    }
}

__global__ __launch_bounds__(256)
void round_copy(const float* __restrict__ in, float* __restrict__ outp)
{
    size_t i = ((size_t)blockIdx.x * 256 + threadIdx.x) * 4;
    float4 v = *(const float4*)(in + i);
    v.x = rndf(v.x); v.y = rndf(v.y); v.z = rndf(v.z); v.w = rndf(v.w);
    *(float4*)(outp + i) = v;
}

// ============================================================================
// In-place row softmax over rows of length 2048.
// ============================================================================
__global__ __launch_bounds__(256)
void softmax2048(float* __restrict__ att)
{
    float* p = att + (size_t)blockIdx.x * NDIM;
    const int t = threadIdx.x;

    float x[8];
    *(float4*)&x[0] = *(const float4*)(p + t * 4);
    *(float4*)&x[4] = *(const float4*)(p + 1024 + t * 4);

    float mx = x[0];
    #pragma unroll
    for (int i = 1; i < 8; i++) mx = fmaxf(mx, x[i]);
    #pragma unroll
    for (int o = 16; o > 0; o >>= 1) mx = fmaxf(mx, __shfl_xor_sync(0xffffffffu, mx, o));

    __shared__ float rmax[8], rsum[8];
    if ((t & 31) == 0) rmax[t >> 5] = mx;
    __syncthreads();
    mx = rmax[0];
    #pragma unroll
    for (int w = 1; w < 8; w++) mx = fmaxf(mx, rmax[w]);

    float s = 0.f;
    #pragma unroll
    for (int i = 0; i < 8; i++) { x[i] = __expf(x[i] - mx); s += x[i]; }
    #pragma unroll
    for (int o = 16; o > 0; o >>= 1) s += __shfl_xor_sync(0xffffffffu, s, o);
    if ((t & 31) == 0) rsum[t >> 5] = s;
    __syncthreads();
    s = 0.f;
    #pragma unroll
    for (int w = 0; w < 8; w++) s += rsum[w];

    float inv = 1.0f / s;
    #pragma unroll
    for (int i = 0; i < 8; i++) x[i] *= inv;
    *(float4*)(p + t * 4)        = *(float4*)&x[0];
    *(float4*)(p + 1024 + t * 4) = *(float4*)&x[4];
}

// ============================================================================
// BatchNorm
// ============================================================================
__global__ __launch_bounds__(256)
void bn_stats(const float* __restrict__ outp,
              float* __restrict__ mean, float* __restrict__ rstd)
{
    const int c = blockIdx.x;
    const int t = threadIdx.x;
    float s = 0.f, ss = 0.f;
    for (int b = 0; b < BATCH; b++) {
        const float* p = outp + (size_t)b * CDIM * NDIM + (size_t)c * NDIM;
        for (int a = t; a < NDIM; a += 256) {
            float x = p[a];
            s += x;
            ss = fmaf(x, x, ss);
        }
    }
    #pragma unroll
    for (int o = 16; o > 0; o >>= 1) {
        s  += __shfl_xor_sync(0xffffffffu, s,  o);
        ss += __shfl_xor_sync(0xffffffffu, ss, o);
    }
    __shared__ float rs[8], rss[8];
    if ((t & 31) == 0) { rs[t >> 5] = s; rss[t >> 5] = ss; }
    __syncthreads();
    if (t == 0) {
        float S = 0.f, SS = 0.f;
        #pragma unroll
        for (int w = 0; w < 8; w++) { S += rs[w]; SS += rss[w]; }
        const float invN = 1.0f / (float)(BATCH * NDIM);
        float m = S * invN;
        float var = SS * invN - m * m;
        mean[c] = m;
        rstd[c] = rsqrtf(var + 1e-5f);
    }
}

__global__ __launch_bounds__(256)
void bn_norm(float* __restrict__ outp,
             const float* __restrict__ mean, const float* __restrict__ rstd,
             const float* __restrict__ gamma, const float* __restrict__ beta)
{
    size_t i = ((size_t)blockIdx.x * 256 + threadIdx.x) * 4;
    int c = (int)((i / NDIM) % CDIM);
    float m = mean[c], r = rstd[c];
    float sc = r * gamma[c];
    float sh = beta[c] - m * sc;
    float4 v = *(float4*)(outp + i);
    v.x = fmaf(v.x, sc, sh);
    v.y = fmaf(v.y, sc, sh);
    v.z = fmaf(v.z, sc, sh);
    v.w = fmaf(v.w, sc, sh);
    *(float4*)(outp + i) = v;
}

// ============================================================================
extern "C" void kernel_launch(void* const* d_in, const int* in_sizes, int n_in,
                              void* d_out, int out_size)
{
    (void)in_sizes; (void)n_in; (void)out_size;
    const float* input_A = (const float*)d_in[0];
    const float* input_B = (const float*)d_in[1];
    const float* W_A     = (const float*)d_in[2];
    const float* W_B     = (const float*)d_in[3];
    const float* W_Bh    = (const float*)d_in[4];
    const float* W_out   = (const float*)d_in[5];
    const float* gamma   = (const float*)d_in[6];
    const float* beta    = (const float*)d_in[7];

    float* out = (float*)d_out;
    float* att = out + (size_t)BATCH * CDIM * NDIM;

    float *inA_t, *inB_t, *WA_r, *WB_r, *WBh_r, *Wout_r;
    float *aproj_t, *bp_t, *bh, *out1_t, *mean, *rstd;
    cudaGetSymbolAddress((void**)&inA_t,   g_inA_t);
    cudaGetSymbolAddress((void**)&inB_t,   g_inB_t);
    cudaGetSymbolAddress((void**)&WA_r,    g_WA_r);
    cudaGetSymbolAddress((void**)&WB_r,    g_WB_r);
    cudaGetSymbolAddress((void**)&WBh_r,   g_WBh_r);
    cudaGetSymbolAddress((void**)&Wout_r,  g_Wout_r);
    cudaGetSymbolAddress((void**)&aproj_t, g_aproj_t);
    cudaGetSymbolAddress((void**)&bp_t,    g_bp_t);
    cudaGetSymbolAddress((void**)&bh,      g_bh);
    cudaGetSymbolAddress((void**)&out1_t,  g_out1_t);
    cudaGetSymbolAddress((void**)&mean,    g_mean);
    cudaGetSymbolAddress((void**)&rstd,    g_rstd);

    cudaFuncSetAttribute(gemm_pipe<true,  false>, cudaFuncAttributeMaxDynamicSharedMemorySize, SMEM_BYTES);
    cudaFuncSetAttribute(gemm_pipe<false, false>, cudaFuncAttributeMaxDynamicSharedMemorySize, SMEM_BYTES);
    cudaFuncSetAttribute(gemm_pipe<true,  true>,  cudaFuncAttributeMaxDynamicSharedMemorySize, SMEM_BYTES);

    const dim3 blk(256);
    const size_t sNC = (size_t)NDIM * CDIM;
    const size_t sNE = (size_t)NDIM * EDIM;
    const size_t sEN = (size_t)EDIM * NDIM;
    const size_t sCN = (size_t)CDIM * NDIM;
    const size_t sNN = (size_t)NDIM * NDIM;

    // 0) preprocess: transpose+round inputs, round weights
    dim3 gt(NDIM / 32, CDIM / 32, BATCH);
    transpose_round<<<gt, dim3(32, 8)>>>(input_A, inA_t);
    transpose_round<<<gt, dim3(32, 8)>>>(input_B, inB_t);
    round_copy<<<(EDIM * CDIM) / 1024, blk>>>(W_A,   WA_r);
    round_copy<<<(EDIM * CDIM) / 1024, blk>>>(W_B,   WB_r);
    round_copy<<<(EDIM * CDIM) / 1024, blk>>>(W_Bh,  WBh_r);
    round_copy<<<(CDIM * EDIM) / 1024, blk>>>(W_out, Wout_r);

    // 1) projections
    // aproj_t[pos][e]: m=pos(2048), n=e(256), k=c(512)
    dim3 gpa(EDIM / 128, NDIM / 128, BATCH);
    gemm_pipe<true, false><<<gpa, blk, SMEM_BYTES>>>(inA_t, WA_r, aproj_t, CDIM, CDIM, CDIM, EDIM, sNC, 0, sNE, 1.f);
    gemm_pipe<true, false><<<gpa, blk, SMEM_BYTES>>>(inB_t, WB_r, bp_t,    CDIM, CDIM, CDIM, EDIM, sNC, 0, sNE, 1.f);
    // bh[e][pos]: m=e(256), n=pos(2048), k=c(512)
    dim3 gpb(NDIM / 128, EDIM / 128, BATCH);
    gemm_pipe<true, false><<<gpb, blk, SMEM_BYTES>>>(WBh_r, inB_t, bh,     CDIM, CDIM, CDIM, NDIM, 0, sNC, sEN, 1.f);

    // 2) h[a][b] = (aproj_t · bp_t^T)/16 : m=a, n=b, k=e(256)
    dim3 gh(NDIM / 128, NDIM / 128, BATCH);
    gemm_pipe<false, false><<<gh, blk, SMEM_BYTES>>>(aproj_t, bp_t, att, EDIM, EDIM, EDIM, NDIM, sNE, sNE, sNN, 0.0625f);

    // 3) in-place softmax (no extra rounded copy)
    softmax2048<<<BATCH * NDIM, blk>>>(att);

    // 4) out1_t[a][e]: m=a(2048), n=e(256), k=pos(2048); A=raw att -> CVT_A
    dim3 g4(EDIM / 128, NDIM / 128, BATCH);
    gemm_pipe<true, true><<<g4, blk, SMEM_BYTES>>>(att, bh, out1_t, NDIM, NDIM, NDIM, EDIM, sNN, sEN, sNE, 1.f);

    // 5) out[c][a]: m=c(512), n=a(2048), k=e(256)
    dim3 g5(NDIM / 128, CDIM / 128, BATCH);
    gemm_pipe<false, false><<<g5, blk, SMEM_BYTES>>>(Wout_r, out1_t, out, EDIM, EDIM, EDIM, NDIM, 0, sNE, sCN, 1.f);

    // 6) BatchNorm
    bn_stats<<<CDIM, blk>>>(out, mean, rstd);
    bn_norm<<<(BATCH * CDIM * NDIM) / 1024, blk>>>(out, mean, rstd, gamma, beta);
}